// round 6
// baseline (speedup 1.0000x reference)
#include <cuda_runtime.h>
#include <stdint.h>

#define N_NODES 50000
#define N_EDGES 800000
#define D 96
#define DC 24            // D / 4 (float4 chunks per row)
#define GEMM_ROWS 32
#define GEMM_THREADS 192
#define SCAN_THREADS 1024

// Scratch (device globals; no allocation allowed)
__device__ int   g_is64;
__device__ float g_deg[N_NODES];                // weighted in-degree (excl. self)
__device__ int   g_cnt[N_NODES];                // edge count per col
__device__ int   g_cursor[N_NODES];             // placement cursors
__device__ int   g_off[N_NODES + 1];            // CSR offsets
__device__ float g_dinv[N_NODES];
__device__ float g_h[(size_t)N_NODES * D];      // stores h * dinv[row]
__device__ int2  g_srt[N_EDGES];                // sorted-by-col: {row, bits(ew*dinv[col])}

__device__ __forceinline__ int load_idx(const void* ei, size_t k) {
    return g_is64 ? (int)((const long long*)ei)[k] : ((const int*)ei)[k];
}

// ---------------------------------------------------------------------------
// 1. zero scratch + detect edge_index dtype (int64 values < 2^31 have
//    all-zero odd int32 words; random int32 node ids do not).
// ---------------------------------------------------------------------------
__global__ void zero_kernel(const int* __restrict__ ei32) {
    int i = blockIdx.x * blockDim.x + threadIdx.x;
    if (i < N_NODES) {
        g_deg[i] = 0.0f;
        g_cnt[i] = 0;
        g_cursor[i] = 0;
    }
    if (i == 0) {
        int looks64 = 1, any_nonzero = 0;
        #pragma unroll
        for (int k = 0; k < 64; k++) {
            if (ei32[2 * k + 1] != 0) looks64 = 0;
            if (ei32[2 * k] != 0) any_nonzero = 1;
        }
        g_is64 = (looks64 && any_nonzero) ? 1 : 0;
    }
}

// ---------------------------------------------------------------------------
// 2. deg[col] += ew ; cnt[col] += 1
// ---------------------------------------------------------------------------
__global__ void accum_deg_kernel(const void* __restrict__ ei,
                                 const float* __restrict__ ew) {
    int e = blockIdx.x * blockDim.x + threadIdx.x;
    if (e < N_EDGES) {
        int col = load_idx(ei, (size_t)N_EDGES + e);
        atomicAdd(&g_deg[col], ew[e]);
        atomicAdd(&g_cnt[col], 1);
    }
}

// ---------------------------------------------------------------------------
// 3. single-block exclusive scan of g_cnt -> g_off ; dinv = rsqrt(deg + 1)
//    (the +1 is the self-loop weight)
// ---------------------------------------------------------------------------
__global__ __launch_bounds__(SCAN_THREADS)
void scan_kernel() {
    __shared__ int part[SCAN_THREADS];
    const int CH = (N_NODES + SCAN_THREADS - 1) / SCAN_THREADS;  // 49
    int t = threadIdx.x;
    int beg = t * CH;
    int end = min(beg + CH, N_NODES);

    int s = 0;
    for (int i = beg; i < end; i++) s += g_cnt[i];
    part[t] = s;
    __syncthreads();

    // Kogge-Stone inclusive scan over partials
    #pragma unroll
    for (int ofs = 1; ofs < SCAN_THREADS; ofs <<= 1) {
        int v = (t >= ofs) ? part[t - ofs] : 0;
        __syncthreads();
        part[t] += v;
        __syncthreads();
    }

    int run = part[t] - s;  // exclusive prefix for this chunk
    for (int i = beg; i < end; i++) {
        g_off[i] = run;
        run += g_cnt[i];
        g_dinv[i] = rsqrtf(g_deg[i] + 1.0f);
    }
    if (t == SCAN_THREADS - 1) g_off[N_NODES] = part[SCAN_THREADS - 1];
}

// ---------------------------------------------------------------------------
// 4. placement: counting-sort edges by col; store {row, ew*dinv[col]}
// ---------------------------------------------------------------------------
__global__ void place_kernel(const void* __restrict__ ei,
                             const float* __restrict__ ew) {
    int e = blockIdx.x * blockDim.x + threadIdx.x;
    if (e < N_EDGES) {
        int row = load_idx(ei, e);
        int col = load_idx(ei, (size_t)N_EDGES + e);
        float nrm = ew[e] * g_dinv[col];
        int pos = g_off[col] + atomicAdd(&g_cursor[col], 1);
        g_srt[pos] = make_int2(row, __float_as_int(nrm));
    }
}

// ---------------------------------------------------------------------------
// 5. GEMM:  h' = (x @ W) * dinv[row]  -> g_h
// ---------------------------------------------------------------------------
__global__ __launch_bounds__(GEMM_THREADS)
void gemm_kernel(const float* __restrict__ x, const float* __restrict__ W) {
    __shared__ float Ws[D * D];
    __shared__ float Xs[GEMM_ROWS * D];

    int tid = threadIdx.x;
    int row0 = blockIdx.x * GEMM_ROWS;

    const float4* W4 = (const float4*)W;
    float4* Ws4 = (float4*)Ws;
    #pragma unroll
    for (int i = tid; i < D * DC; i += GEMM_THREADS) Ws4[i] = W4[i];

    const float4* X4 = (const float4*)x;
    float4* Xs4 = (float4*)Xs;
    #pragma unroll
    for (int i = tid; i < GEMM_ROWS * DC; i += GEMM_THREADS) {
        int r = i / DC;
        int c = i - r * DC;
        int gr = row0 + r;
        Xs4[i] = (gr < N_NODES) ? X4[(size_t)gr * DC + c]
                                : make_float4(0.f, 0.f, 0.f, 0.f);
    }
    __syncthreads();

    int tx = tid % DC;       // output float4 chunk
    int ty = tid / DC;       // row group 0..7
    int rbase = ty * 4;

    float4 acc[4];
    #pragma unroll
    for (int r = 0; r < 4; r++) acc[r] = make_float4(0.f, 0.f, 0.f, 0.f);

    #pragma unroll 4
    for (int kc = 0; kc < DC; kc++) {
        float4 xv[4];
        #pragma unroll
        for (int r = 0; r < 4; r++) xv[r] = Xs4[(rbase + r) * DC + kc];
        #pragma unroll
        for (int kk = 0; kk < 4; kk++) {
            float4 wv = Ws4[(kc * 4 + kk) * DC + tx];
            #pragma unroll
            for (int r = 0; r < 4; r++) {
                float a = ((const float*)&xv[r])[kk];
                acc[r].x += a * wv.x; acc[r].y += a * wv.y;
                acc[r].z += a * wv.z; acc[r].w += a * wv.w;
            }
        }
    }

    float4* H4 = (float4*)g_h;
    #pragma unroll
    for (int r = 0; r < 4; r++) {
        int gr = row0 + rbase + r;
        if (gr < N_NODES) {
            float s = g_dinv[gr];
            float4 hv;
            hv.x = acc[r].x * s; hv.y = acc[r].y * s;
            hv.z = acc[r].z * s; hv.w = acc[r].w * s;
            H4[(size_t)gr * DC + tx] = hv;
        }
    }
}

// ---------------------------------------------------------------------------
// 6. Gather (atomic-free): one warp per node.
//    out[n] = b + h'[n]*dinv[n] + sum_{e: col=n} h'[row_e] * norm_e
// ---------------------------------------------------------------------------
__global__ __launch_bounds__(256)
void gather_kernel(const float* __restrict__ b, float* __restrict__ out) {
    int node = (blockIdx.x * blockDim.x + threadIdx.x) >> 5;
    int lane = threadIdx.x & 31;
    if (node >= N_NODES) return;

    int beg = g_off[node];
    int end = g_off[node + 1];

    const float4* H4 = (const float4*)g_h;
    float4 acc = make_float4(0.f, 0.f, 0.f, 0.f);

    for (int base = beg; base < end; base += 32) {
        int n_k = min(32, end - base);
        int2 meta = make_int2(0, 0);
        if (lane < n_k) meta = g_srt[base + lane];   // coalesced
        #pragma unroll 4
        for (int j = 0; j < n_k; j++) {
            int row = __shfl_sync(0xffffffffu, meta.x, j);
            float nrm = __int_as_float(__shfl_sync(0xffffffffu, meta.y, j));
            if (lane < DC) {
                float4 hv = H4[(size_t)row * DC + lane];
                acc.x += hv.x * nrm; acc.y += hv.y * nrm;
                acc.z += hv.z * nrm; acc.w += hv.w * nrm;
            }
        }
    }

    if (lane < DC) {
        float s = g_dinv[node];
        float4 hn = H4[(size_t)node * DC + lane];
        float4 bv = ((const float4*)b)[lane];
        float4 o;
        o.x = bv.x + hn.x * s + acc.x;
        o.y = bv.y + hn.y * s + acc.y;
        o.z = bv.z + hn.z * s + acc.z;
        o.w = bv.w + hn.w * s + acc.w;
        ((float4*)out)[(size_t)node * DC + lane] = o;
    }
}

// ---------------------------------------------------------------------------
// Launch.  Inputs: x[N*96] f32, edge_index[2*E] int32/int64, edge_weight[E] f32,
//                  W[96*96] f32, b[96] f32.  Output: [N*96] f32.
// ---------------------------------------------------------------------------
extern "C" void kernel_launch(void* const* d_in, const int* in_sizes, int n_in,
                              void* d_out, int out_size) {
    const float* x = (const float*)d_in[0];
    const void* ei = d_in[1];
    const float* ew = (const float*)d_in[2];
    const float* W = (const float*)d_in[3];
    const float* b = (const float*)d_in[4];
    float* out = (float*)d_out;

    zero_kernel<<<(N_NODES + 255) / 256, 256>>>((const int*)ei);
    accum_deg_kernel<<<(N_EDGES + 255) / 256, 256>>>(ei, ew);
    scan_kernel<<<1, SCAN_THREADS>>>();
    place_kernel<<<(N_EDGES + 255) / 256, 256>>>(ei, ew);
    gemm_kernel<<<(N_NODES + GEMM_ROWS - 1) / GEMM_ROWS, GEMM_THREADS>>>(x, W);
    gather_kernel<<<(N_NODES * 32 + 255) / 256, 256>>>(b, out);
}

// round 7
// speedup vs baseline: 1.7959x; 1.7959x over previous
#include <cuda_runtime.h>
#include <stdint.h>

#define N_NODES 50000
#define N_EDGES 800000
#define D 96
#define DC 24            // D / 4 (float4 chunks per row)
#define GEMM_ROWS 32
#define GEMM_THREADS 192

// Scratch (device globals; no allocation allowed)
__device__ int   g_is64;
__device__ float g_deg[N_NODES];
__device__ float g_dinv[N_NODES];
__device__ float g_h[(size_t)N_NODES * D];     // stores h * dinv[row]

__device__ __forceinline__ int load_idx(const void* ei, size_t k) {
    return g_is64 ? (int)((const long long*)ei)[k] : ((const int*)ei)[k];
}

// packed f32x2 helpers (sm_103a FFMA2 — PTX only)
__device__ __forceinline__ unsigned long long pack2(float x, float y) {
    unsigned long long p;
    asm("mov.b64 %0, {%1, %2};" : "=l"(p) : "f"(x), "f"(y));
    return p;
}
__device__ __forceinline__ void fma2(unsigned long long& acc,
                                     unsigned long long a,
                                     unsigned long long b) {
    asm("fma.rn.f32x2 %0, %1, %2, %0;" : "+l"(acc) : "l"(a), "l"(b));
}
__device__ __forceinline__ void unpack2(unsigned long long p, float& x, float& y) {
    asm("mov.b64 {%0, %1}, %2;" : "=f"(x), "=f"(y) : "l"(p));
}

// ---------------------------------------------------------------------------
// 1. init: deg = 1 (self loop weight); thread 0 detects edge_index dtype.
//    int64 values < 2^31 have all-zero odd int32 words; random int32 ids don't.
// ---------------------------------------------------------------------------
__global__ void init_kernel(const int* __restrict__ ei32) {
    int i = blockIdx.x * blockDim.x + threadIdx.x;
    if (i < N_NODES) g_deg[i] = 1.0f;
    if (i == 0) {
        int looks64 = 1, any_nonzero = 0;
        #pragma unroll
        for (int k = 0; k < 64; k++) {
            if (ei32[2 * k + 1] != 0) looks64 = 0;
            if (ei32[2 * k] != 0) any_nonzero = 1;
        }
        g_is64 = (looks64 && any_nonzero) ? 1 : 0;
    }
}

// ---------------------------------------------------------------------------
// 2. deg[col] += ew
// ---------------------------------------------------------------------------
__global__ void accum_deg_kernel(const void* __restrict__ ei,
                                 const float* __restrict__ ew) {
    int e = blockIdx.x * blockDim.x + threadIdx.x;
    if (e < N_EDGES) {
        int col = load_idx(ei, (size_t)N_EDGES + e);
        atomicAdd(&g_deg[col], ew[e]);
    }
}

// ---------------------------------------------------------------------------
// 3. dinv = rsqrt(deg)
// ---------------------------------------------------------------------------
__global__ void dinv_kernel() {
    int i = blockIdx.x * blockDim.x + threadIdx.x;
    if (i < N_NODES) {
        float d = g_deg[i];
        g_dinv[i] = (d > 0.0f) ? rsqrtf(d) : 0.0f;
    }
}

// ---------------------------------------------------------------------------
// 4. GEMM + epilogue:  h' = (x @ W) * dinv[row]  -> g_h
//                      out[row] = b + h' * dinv[row]   (self loop + bias)
//    Inner loop uses packed fma.rn.f32x2 (FFMA2) on 64-bit accumulators.
// ---------------------------------------------------------------------------
__global__ __launch_bounds__(GEMM_THREADS)
void gemm_kernel(const float* __restrict__ x, const float* __restrict__ W,
                 const float* __restrict__ b, float* __restrict__ out) {
    __shared__ float Ws[D * D];
    __shared__ float Xs[GEMM_ROWS * D];

    int tid = threadIdx.x;
    int row0 = blockIdx.x * GEMM_ROWS;

    const float4* W4 = (const float4*)W;
    float4* Ws4 = (float4*)Ws;
    #pragma unroll
    for (int i = tid; i < D * DC; i += GEMM_THREADS) Ws4[i] = W4[i];

    const float4* X4 = (const float4*)x;
    float4* Xs4 = (float4*)Xs;
    #pragma unroll
    for (int i = tid; i < GEMM_ROWS * DC; i += GEMM_THREADS) {
        int r = i / DC;
        int c = i - r * DC;
        int gr = row0 + r;
        Xs4[i] = (gr < N_NODES) ? X4[(size_t)gr * DC + c]
                                : make_float4(0.f, 0.f, 0.f, 0.f);
    }
    __syncthreads();

    int tx = tid % DC;       // output float4 chunk
    int ty = tid / DC;       // row group 0..7
    int rbase = ty * 4;

    unsigned long long accXY[4], accZW[4];
    #pragma unroll
    for (int r = 0; r < 4; r++) { accXY[r] = 0ull; accZW[r] = 0ull; }

    #pragma unroll 4
    for (int kc = 0; kc < DC; kc++) {
        float4 xv[4];
        #pragma unroll
        for (int r = 0; r < 4; r++) xv[r] = Xs4[(rbase + r) * DC + kc];
        #pragma unroll
        for (int kk = 0; kk < 4; kk++) {
            float4 wv = Ws4[(kc * 4 + kk) * DC + tx];
            unsigned long long wXY = pack2(wv.x, wv.y);
            unsigned long long wZW = pack2(wv.z, wv.w);
            #pragma unroll
            for (int r = 0; r < 4; r++) {
                float a = ((const float*)&xv[r])[kk];
                unsigned long long aa = pack2(a, a);
                fma2(accXY[r], aa, wXY);
                fma2(accZW[r], aa, wZW);
            }
        }
    }

    float4 bv = ((const float4*)b)[tx];
    float4* H4 = (float4*)g_h;
    float4* O4 = (float4*)out;
    #pragma unroll
    for (int r = 0; r < 4; r++) {
        int gr = row0 + rbase + r;
        if (gr < N_NODES) {
            float s = g_dinv[gr];
            float4 av;
            unpack2(accXY[r], av.x, av.y);
            unpack2(accZW[r], av.z, av.w);
            float4 hv;  // h * dinv
            hv.x = av.x * s; hv.y = av.y * s;
            hv.z = av.z * s; hv.w = av.w * s;
            H4[(size_t)gr * DC + tx] = hv;
            float4 o;   // b + h * dinv^2
            o.x = bv.x + hv.x * s; o.y = bv.y + hv.y * s;
            o.z = bv.z + hv.z * s; o.w = bv.w + hv.w * s;
            O4[(size_t)gr * DC + tx] = o;
        }
    }
}

// ---------------------------------------------------------------------------
// 5. Scatter: thread t -> edge t/24, chunk t%24 (all 32 lanes active).
//    out[col] += h'[row] * (ew[e] * dinv[col])   via red.global.add.v4.f32
//    Edge metadata read directly (broadcast within each 24-thread edge group;
//    dinv is L1-resident at 200KB).
// ---------------------------------------------------------------------------
__global__ __launch_bounds__(256)
void scatter_kernel(const void* __restrict__ ei,
                    const float* __restrict__ ew,
                    float* __restrict__ out) {
    int idx = blockIdx.x * blockDim.x + threadIdx.x;
    if (idx >= N_EDGES * DC) return;
    int e = idx / DC;
    int c = idx - e * DC;
    int row = load_idx(ei, e);
    int col = load_idx(ei, (size_t)N_EDGES + e);
    float nrm = ew[e] * g_dinv[col];
    float4 hv = ((const float4*)g_h)[(size_t)row * DC + c];
    float mx = hv.x * nrm, my = hv.y * nrm, mz = hv.z * nrm, mw = hv.w * nrm;
    float* addr = out + (size_t)col * D + c * 4;
    asm volatile("red.global.add.v4.f32 [%0], {%1, %2, %3, %4};"
                 :: "l"(addr), "f"(mx), "f"(my), "f"(mz), "f"(mw)
                 : "memory");
}

// ---------------------------------------------------------------------------
// Launch.  Inputs: x[N*96] f32, edge_index[2*E] int32/int64, edge_weight[E] f32,
//                  W[96*96] f32, b[96] f32.  Output: [N*96] f32.
// ---------------------------------------------------------------------------
extern "C" void kernel_launch(void* const* d_in, const int* in_sizes, int n_in,
                              void* d_out, int out_size) {
    const float* x = (const float*)d_in[0];
    const void* ei = d_in[1];
    const float* ew = (const float*)d_in[2];
    const float* W = (const float*)d_in[3];
    const float* b = (const float*)d_in[4];
    float* out = (float*)d_out;

    init_kernel<<<(N_NODES + 255) / 256, 256>>>((const int*)ei);
    accum_deg_kernel<<<(N_EDGES + 255) / 256, 256>>>(ei, ew);
    dinv_kernel<<<(N_NODES + 255) / 256, 256>>>();
    gemm_kernel<<<(N_NODES + GEMM_ROWS - 1) / GEMM_ROWS, GEMM_THREADS>>>(x, W, b, out);
    scatter_kernel<<<(N_EDGES * DC + 255) / 256, 256>>>(ei, ew, out);
}

// round 8
// speedup vs baseline: 1.8719x; 1.0423x over previous
#include <cuda_runtime.h>
#include <stdint.h>

#define N_NODES 50000
#define N_EDGES 800000
#define D 96
#define DC 24              // D / 4 (float4 chunks per row)
#define XS_STRIDE 25       // padded row stride in float4 (bank decorrelation)
#define GEMM_ROWS 128      // rows per block
#define GEMM_THREADS 192   // 12 col-groups x 16 row-groups
#define GEMM_SMEM ((D * DC + GEMM_ROWS * XS_STRIDE) * 16)  // Ws + Xs bytes

// Scratch (device globals; no allocation allowed)
__device__ int   g_is64;
__device__ float g_deg[N_NODES];
__device__ float g_h[(size_t)N_NODES * D];     // stores h * dinv[row]

__device__ __forceinline__ int load_idx(const void* ei, size_t k) {
    return g_is64 ? (int)((const long long*)ei)[k] : ((const int*)ei)[k];
}

// packed f32x2 helpers (sm_103a FFMA2 — PTX only)
__device__ __forceinline__ unsigned long long pack2(float x, float y) {
    unsigned long long p;
    asm("mov.b64 %0, {%1, %2};" : "=l"(p) : "f"(x), "f"(y));
    return p;
}
__device__ __forceinline__ void fma2(unsigned long long& acc,
                                     unsigned long long a,
                                     unsigned long long b) {
    asm("fma.rn.f32x2 %0, %1, %2, %0;" : "+l"(acc) : "l"(a), "l"(b));
}
__device__ __forceinline__ void unpack2(unsigned long long p, float& x, float& y) {
    asm("mov.b64 {%0, %1}, %2;" : "=f"(x), "=f"(y) : "l"(p));
}

// ---------------------------------------------------------------------------
// 1. init: deg = 1 (self loop weight); thread 0 detects edge_index dtype.
//    int64 values < 2^31 have all-zero odd int32 words; random int32 ids don't.
// ---------------------------------------------------------------------------
__global__ void init_kernel(const int* __restrict__ ei32) {
    int i = blockIdx.x * blockDim.x + threadIdx.x;
    if (i < N_NODES) g_deg[i] = 1.0f;
    if (i == 0) {
        int looks64 = 1, any_nonzero = 0;
        #pragma unroll
        for (int k = 0; k < 64; k++) {
            if (ei32[2 * k + 1] != 0) looks64 = 0;
            if (ei32[2 * k] != 0) any_nonzero = 1;
        }
        g_is64 = (looks64 && any_nonzero) ? 1 : 0;
    }
}

// ---------------------------------------------------------------------------
// 2. deg[col] += ew
// ---------------------------------------------------------------------------
__global__ void accum_deg_kernel(const void* __restrict__ ei,
                                 const float* __restrict__ ew) {
    int e = blockIdx.x * blockDim.x + threadIdx.x;
    if (e < N_EDGES) {
        int col = load_idx(ei, (size_t)N_EDGES + e);
        atomicAdd(&g_deg[col], ew[e]);
    }
}

// ---------------------------------------------------------------------------
// 3. GEMM + epilogue:  h' = (x @ W) * dinv[row]  -> g_h
//                      out[row] = b + h' * dinv[row]   (self loop + bias)
//    8x8 thread tiles, FFMA2 inner loop, 88KB dynamic smem.
// ---------------------------------------------------------------------------
__global__ __launch_bounds__(GEMM_THREADS)
void gemm_kernel(const float* __restrict__ x, const float* __restrict__ W,
                 const float* __restrict__ b, float* __restrict__ out) {
    extern __shared__ float smem[];
    float4* Ws4 = (float4*)smem;                       // [D][DC]
    float4* Xs4 = (float4*)(smem + D * D);             // [GEMM_ROWS][XS_STRIDE]

    int tid = threadIdx.x;
    int row0 = blockIdx.x * GEMM_ROWS;

    const float4* W4 = (const float4*)W;
    #pragma unroll
    for (int i = tid; i < D * DC; i += GEMM_THREADS) Ws4[i] = W4[i];

    const float4* X4 = (const float4*)x;
    #pragma unroll
    for (int i = tid; i < GEMM_ROWS * DC; i += GEMM_THREADS) {
        int r = i / DC;
        int c = i - r * DC;
        int gr = row0 + r;
        Xs4[r * XS_STRIDE + c] = (gr < N_NODES) ? X4[(size_t)gr * DC + c]
                                                : make_float4(0.f, 0.f, 0.f, 0.f);
    }
    __syncthreads();

    int tx = tid % 12;       // col group: float4 chunks 2*tx, 2*tx+1
    int ty = tid / 12;       // row group 0..15
    int rbase = ty * 8;
    int c0 = 2 * tx, c1 = 2 * tx + 1;

    // acc[r][0..3] = {XY of chunk0, ZW of chunk0, XY of chunk1, ZW of chunk1}
    unsigned long long acc[8][4];
    #pragma unroll
    for (int r = 0; r < 8; r++)
        #pragma unroll
        for (int q = 0; q < 4; q++) acc[r][q] = 0ull;

    #pragma unroll 2
    for (int kc = 0; kc < DC; kc++) {
        float4 xv[8];
        #pragma unroll
        for (int r = 0; r < 8; r++) xv[r] = Xs4[(rbase + r) * XS_STRIDE + kc];
        #pragma unroll
        for (int kk = 0; kk < 4; kk++) {
            float4 wv0 = Ws4[(kc * 4 + kk) * DC + c0];
            float4 wv1 = Ws4[(kc * 4 + kk) * DC + c1];
            unsigned long long w0XY = pack2(wv0.x, wv0.y);
            unsigned long long w0ZW = pack2(wv0.z, wv0.w);
            unsigned long long w1XY = pack2(wv1.x, wv1.y);
            unsigned long long w1ZW = pack2(wv1.z, wv1.w);
            #pragma unroll
            for (int r = 0; r < 8; r++) {
                float a = ((const float*)&xv[r])[kk];
                unsigned long long aa = pack2(a, a);
                fma2(acc[r][0], aa, w0XY);
                fma2(acc[r][1], aa, w0ZW);
                fma2(acc[r][2], aa, w1XY);
                fma2(acc[r][3], aa, w1ZW);
            }
        }
    }

    float4 bv0 = ((const float4*)b)[c0];
    float4 bv1 = ((const float4*)b)[c1];
    float4* H4 = (float4*)g_h;
    float4* O4 = (float4*)out;
    #pragma unroll
    for (int r = 0; r < 8; r++) {
        int gr = row0 + rbase + r;
        if (gr < N_NODES) {
            float s = rsqrtf(g_deg[gr]);
            float4 h0, h1;
            unpack2(acc[r][0], h0.x, h0.y);
            unpack2(acc[r][1], h0.z, h0.w);
            unpack2(acc[r][2], h1.x, h1.y);
            unpack2(acc[r][3], h1.z, h1.w);
            h0.x *= s; h0.y *= s; h0.z *= s; h0.w *= s;
            h1.x *= s; h1.y *= s; h1.z *= s; h1.w *= s;
            H4[(size_t)gr * DC + c0] = h0;
            H4[(size_t)gr * DC + c1] = h1;
            float4 o0, o1;   // b + h*dinv^2
            o0.x = bv0.x + h0.x * s; o0.y = bv0.y + h0.y * s;
            o0.z = bv0.z + h0.z * s; o0.w = bv0.w + h0.w * s;
            o1.x = bv1.x + h1.x * s; o1.y = bv1.y + h1.y * s;
            o1.z = bv1.z + h1.z * s; o1.w = bv1.w + h1.w * s;
            O4[(size_t)gr * DC + c0] = o0;
            O4[(size_t)gr * DC + c1] = o1;
        }
    }
}

// ---------------------------------------------------------------------------
// 4. Scatter: thread t -> edge t/24, chunk t%24 (all 32 lanes active).
//    out[col] += h'[row] * (ew[e] * rsqrt(deg[col]))  via red.global.add.v4.f32
// ---------------------------------------------------------------------------
__global__ __launch_bounds__(256)
void scatter_kernel(const void* __restrict__ ei,
                    const float* __restrict__ ew,
                    float* __restrict__ out) {
    int idx = blockIdx.x * blockDim.x + threadIdx.x;
    if (idx >= N_EDGES * DC) return;
    int e = idx / DC;
    int c = idx - e * DC;
    int row = load_idx(ei, e);
    int col = load_idx(ei, (size_t)N_EDGES + e);
    float nrm = ew[e] * rsqrtf(g_deg[col]);
    float4 hv = ((const float4*)g_h)[(size_t)row * DC + c];
    float mx = hv.x * nrm, my = hv.y * nrm, mz = hv.z * nrm, mw = hv.w * nrm;
    float* addr = out + (size_t)col * D + c * 4;
    asm volatile("red.global.add.v4.f32 [%0], {%1, %2, %3, %4};"
                 :: "l"(addr), "f"(mx), "f"(my), "f"(mz), "f"(mw)
                 : "memory");
}

// ---------------------------------------------------------------------------
// Launch.  Inputs: x[N*96] f32, edge_index[2*E] int32/int64, edge_weight[E] f32,
//                  W[96*96] f32, b[96] f32.  Output: [N*96] f32.
// ---------------------------------------------------------------------------
extern "C" void kernel_launch(void* const* d_in, const int* in_sizes, int n_in,
                              void* d_out, int out_size) {
    const float* x = (const float*)d_in[0];
    const void* ei = d_in[1];
    const float* ew = (const float*)d_in[2];
    const float* W = (const float*)d_in[3];
    const float* b = (const float*)d_in[4];
    float* out = (float*)d_out;

    static int smem_set = 0;
    if (!smem_set) {
        cudaFuncSetAttribute(gemm_kernel,
                             cudaFuncAttributeMaxDynamicSharedMemorySize,
                             GEMM_SMEM);
        smem_set = 1;
    }

    init_kernel<<<(N_NODES + 255) / 256, 256>>>((const int*)ei);
    accum_deg_kernel<<<(N_EDGES + 255) / 256, 256>>>(ei, ew);
    gemm_kernel<<<(N_NODES + GEMM_ROWS - 1) / GEMM_ROWS, GEMM_THREADS, GEMM_SMEM>>>(x, W, b, out);
    scatter_kernel<<<(N_EDGES * DC + 255) / 256, 256>>>(ei, ew, out);
}